// round 12
// baseline (speedup 1.0000x reference)
#include <cuda_runtime.h>
#include <cuda_fp16.h>
#include <math.h>
#include <stdint.h>

#define N_NODES 50000
#define HID 128
#define NODE_DIM 64
#define GRAPH_DIM 32
#define E_MAX 1700000

// ---------------- scratch (static device globals; no allocation) ----------------
__device__ float  g_hA[N_NODES * HID];
__device__ float  g_hB[N_NODES * HID];
__device__ __half g_fsh[N_NODES * HID];
__device__ float  g_fd[N_NODES * HID];
__device__ int    g_off[N_NODES + 1];
__device__ int    g_cur[N_NODES];
__device__ int    g_csrc[E_MAX];          // holds BYTE offsets: src * HID * 2
__device__ float  g_emb_scratch[HID];
// zero-blob: [deg (N)] [pool (HID floats)] [done-counter]
__device__ int    g_zero[N_NODES + HID + 8];
#define G_DEG  (g_zero)
#define G_POOL ((float*)(g_zero + N_NODES))
#define G_CNT  (g_zero + N_NODES + HID)
// prepped fp16 weights, permuted fragment layout. KP2(128)=72 words/row, KP2(64)=40.
__device__ uint4  g_Whs[3][128 * 72 / 4];
__device__ uint4  g_Whd[3][128 * 72 / 4];
__device__ uint4  g_Whin[128 * 40 / 4];

// ---------------- fp16 tensor-core GEMM core (m16n8k16, fp32 accum) ----------------
__device__ __forceinline__ void mma_f16(float* c, const uint32_t* a, const uint32_t* b) {
    asm volatile(
        "mma.sync.aligned.m16n8k16.row.col.f32.f16.f16.f32 "
        "{%0,%1,%2,%3}, {%4,%5,%6,%7}, {%8,%9}, {%0,%1,%2,%3};"
        : "+f"(c[0]), "+f"(c[1]), "+f"(c[2]), "+f"(c[3])
        : "r"(a[0]), "r"(a[1]), "r"(a[2]), "r"(a[3]), "r"(b[0]), "r"(b[1]));
}

// A tile loader: fp32 [TR x K] gmem -> permuted fp16 smem (KP2 = K/2+8 words/row)
template <int K, int TR>
__device__ __forceinline__ void load_a_tile(const float* __restrict__ A, uint32_t* sA, int row0) {
    constexpr int KP2 = K / 2 + 8;
    const int o0tab[4] = {0, 4, 1, 5};
    const int o1tab[4] = {2, 6, 3, 7};
    int tid = threadIdx.x;
    for (int i = tid; i < TR * (K / 4); i += 256) {
        int r = i / (K / 4);
        int q = i % (K / 4);
        int row = row0 + r;
        float4 v = make_float4(0.f, 0.f, 0.f, 0.f);
        if (row < N_NODES) v = *(const float4*)(A + (size_t)row * K + q * 4);
        int base = r * KP2 + (q >> 2) * 8;
        __half2 h01 = __floats2half2_rn(v.x, v.y);
        __half2 h23 = __floats2half2_rn(v.z, v.w);
        sA[base + o0tab[q & 3]] = *(uint32_t*)&h01;
        sA[base + o1tab[q & 3]] = *(uint32_t*)&h23;
    }
}

// mainloop + epilogue over a TR x 128 tile. Ch != nullptr -> fp16 output, else fp32 to Cf.
template <int K, int TR>
__device__ __forceinline__ void gemm_core(const uint32_t* sA, const uint32_t* sB, int row0,
                                          const float* __restrict__ bias,
                                          float* __restrict__ Cf, __half* __restrict__ Ch) {
    constexpr int KP2 = K / 2 + 8;
    constexpr int RPM = TR / 4;     // rows per mwarp
    constexpr int NT  = TR / 64;    // 16-row pair groups per mwarp
    int tid = threadIdx.x;
    int warp = tid >> 5;
    int lane = tid & 31;
    int mwarp = warp >> 1;
    int nwarp = warp & 1;
    int g = lane >> 2;
    int tg = lane & 3;

    float acc[NT][8][4];
#pragma unroll
    for (int t = 0; t < NT; t++)
#pragma unroll
        for (int j = 0; j < 8; j++) { acc[t][j][0] = acc[t][j][1] = acc[t][j][2] = acc[t][j][3] = 0.f; }

    int rb = mwarp * RPM + g;
#pragma unroll
    for (int ks = 0; ks < K / 16; ks++) {
        int kk = ks * 8 + tg * 2;
        uint32_t afr[NT][4];
#pragma unroll
        for (int t = 0; t < NT; t++) {
            uint2 a0 = *(const uint2*)(sA + (rb + t * 16)     * KP2 + kk);
            uint2 a1 = *(const uint2*)(sA + (rb + t * 16 + 8) * KP2 + kk);
            afr[t][0] = a0.x; afr[t][1] = a1.x; afr[t][2] = a0.y; afr[t][3] = a1.y;
        }
        uint32_t bfr[8][2];
#pragma unroll
        for (int j = 0; j < 8; j++) {
            int n0 = nwarp * 64 + j * 8 + g;
            uint2 b = *(const uint2*)(sB + n0 * KP2 + kk);
            bfr[j][0] = b.x; bfr[j][1] = b.y;
        }
#pragma unroll
        for (int t = 0; t < NT; t++)
#pragma unroll
            for (int j = 0; j < 8; j++) mma_f16(acc[t][j], afr[t], bfr[j]);
    }

#pragma unroll
    for (int t = 0; t < NT; t++) {
        int rbase = row0 + mwarp * RPM + t * 16 + g;
#pragma unroll
        for (int j = 0; j < 8; j++) {
            int col = nwarp * 64 + j * 8 + tg * 2;
            float bx = __ldg(bias + col);
            float by = __ldg(bias + col + 1);
            float v0x = acc[t][j][0] + bx, v0y = acc[t][j][1] + by;
            float v1x = acc[t][j][2] + bx, v1y = acc[t][j][3] + by;
            if (Ch) {
                if (rbase < N_NODES)
                    *(__half2*)(Ch + (size_t)rbase * HID + col) = __floats2half2_rn(v0x, v0y);
                if (rbase + 8 < N_NODES)
                    *(__half2*)(Ch + (size_t)(rbase + 8) * HID + col) = __floats2half2_rn(v1x, v1y);
            } else {
                if (rbase < N_NODES)
                    *(float2*)(Cf + (size_t)rbase * HID + col) = make_float2(v0x, v0y);
                if (rbase + 8 < N_NODES)
                    *(float2*)(Cf + (size_t)(rbase + 8) * HID + col) = make_float2(v1x, v1y);
            }
        }
    }
}

// ---------------- MEGA kernel: count + (last block) scan + weight prep + gemm_in ----------
__global__ void __launch_bounds__(256) mega_kernel(
    const int* __restrict__ dst, int E, int nbCnt,
    const float* __restrict__ W_in, const float* __restrict__ W_src, const float* __restrict__ W_dst,
    uint32_t* __restrict__ o_in, uint32_t* __restrict__ o_src, uint32_t* __restrict__ o_dst,
    const float* __restrict__ node_feats, const float* __restrict__ b_in, float* __restrict__ hA)
{
    int bx = blockIdx.x;
    int tid = threadIdx.x;

    if (bx < nbCnt) {
        int e = bx * 256 + tid;
        if (e < E) atomicAdd(&G_DEG[dst[e]], 1);
        __syncthreads();
        __threadfence();
        __shared__ int is_last;
        if (tid == 0) {
            int d = atomicAdd(G_CNT, 1);
            is_last = (d == nbCnt - 1);
        }
        __syncthreads();
        if (is_last) {
            __threadfence();
            __shared__ int sums[256];
            const int CH = (N_NODES + 255) / 256;
            int st = tid * CH;
            int en = st + CH; if (en > N_NODES) en = N_NODES;
            if (st > N_NODES) st = N_NODES;
            int s = 0;
            for (int i = st; i < en; i++) s += G_DEG[i];
            sums[tid] = s;
            __syncthreads();
            for (int d = 1; d < 256; d <<= 1) {
                int v = (tid >= d) ? sums[tid - d] : 0;
                __syncthreads();
                sums[tid] += v;
                __syncthreads();
            }
            int run = (tid == 0) ? 0 : sums[tid - 1];
            for (int i = st; i < en; i++) {
                g_off[i] = run;
                g_cur[i] = run;
                run += G_DEG[i];
            }
            if (tid == 255) g_off[N_NODES] = sums[255];
        }
        return;
    }
    bx -= nbCnt;

    if (bx < 208) {
        const float* W; uint32_t* out; int K; int inner;
        if (bx < 16) { W = W_in; out = o_in; K = 64; inner = bx; }
        else {
            int b2 = bx - 16;
            int which = b2 >> 5;
            inner = b2 & 31;
            int l = which % 3;
            if (which < 3) { W = W_src + (size_t)l * HID * HID; out = o_src + (size_t)l * (128 * 72); }
            else           { W = W_dst + (size_t)l * HID * HID; out = o_dst + (size_t)l * (128 * 72); }
            K = 128;
        }
        int half_k = K >> 1;
        int idx = inner * 256 + tid;
        if (idx >= 128 * half_k) return;
        int n = idx / half_k;
        int k = (idx % half_k) * 2;
        float x = W[(size_t)k * HID + n];
        float y = W[(size_t)(k + 1) * HID + n];
        int KP2 = half_k + 8;
        int uu = (k & 15) >> 1;
        int o = (uu & 3) * 2 + (uu >> 2);
        __half2 h = __floats2half2_rn(x, y);
        out[n * KP2 + (k >> 4) * 8 + o] = *(uint32_t*)&h;
        return;
    }
    bx -= 208;

    {
        constexpr int KP2 = 64 / 2 + 8;
        extern __shared__ uint32_t smem_u[];
        uint32_t* sA = smem_u;
        uint32_t* sB = smem_u + 128 * KP2;
        int row0 = bx * 128;
        load_a_tile<64, 128>(node_feats, sA, row0);
        for (int i = tid; i < 128 * 32; i += 256) {
            int n = i >> 5;
            int k = (i & 31) * 2;
            float x = W_in[(size_t)k * HID + n];
            float y = W_in[(size_t)(k + 1) * HID + n];
            int uu = (k & 15) >> 1;
            int o = (uu & 3) * 2 + (uu >> 2);
            __half2 h = __floats2half2_rn(x, y);
            sB[n * KP2 + (k >> 4) * 8 + o] = *(uint32_t*)&h;
        }
        __syncthreads();
        gemm_core<64, 128>(sA, sB, row0, b_in, hA, nullptr);
    }
}

// ---------------- scatter (stores BYTE offsets src*256) ----------------
__global__ void scatter_kernel(const int* __restrict__ src, const int* __restrict__ dst, int E) {
    int e = blockIdx.x * blockDim.x + threadIdx.x;
    if (e < E) {
        int d = dst[e];
        int pos = atomicAdd(&g_cur[d], 1);
        g_csrc[pos] = src[e] << 8;          // HID * sizeof(half) = 256
    }
}

// ---------------- dual GEMM: 64-row tiles for 3 CTAs/SM ----------------
__global__ void __launch_bounds__(256, 3) gemm_dual_kernel(
    const float* __restrict__ A,
    const uint4* __restrict__ Wh1, const float* __restrict__ b1, __half* __restrict__ C1h,
    const uint4* __restrict__ Wh2, const float* __restrict__ b2, float* __restrict__ C2)
{
    constexpr int KP2 = 128 / 2 + 8;      // 72
    extern __shared__ uint32_t smem_u[];
    uint32_t* sA = smem_u;                // [64][72]
    uint32_t* sB = smem_u + 64 * KP2;     // [128][72]

    const uint4* Wh; const float* bias;
    if (blockIdx.y == 0) { Wh = Wh1; bias = b1; }
    else                 { Wh = Wh2; bias = b2; }

    int row0 = blockIdx.x * 64;
    load_a_tile<128, 64>(A, sA, row0);
    {
        uint4* dstp = (uint4*)sB;
        for (int i = threadIdx.x; i < 128 * KP2 / 4; i += 256) dstp[i] = Wh[i];
    }
    __syncthreads();
    if (blockIdx.y == 0) gemm_core<128, 64>(sA, sB, row0, bias, nullptr, C1h);
    else                 gemm_core<128, 64>(sA, sB, row0, bias, C2, nullptr);
}

// ---------------- GATv2 layer: warp/node, half-warp/edge, abs-trick half2 logits ----------
// leaky(x) = 0.6x + 0.4|x|  ->  pd += x*(0.6a) + |x|*(0.4a)
template <bool DO_POOL>
__global__ void __launch_bounds__(256) gat_layer_kernel(
    const __half* __restrict__ fsh, const float* __restrict__ fd,
    const float* __restrict__ h_in, const float* __restrict__ attn,
    const float* __restrict__ lng, const float* __restrict__ lnb,
    float* __restrict__ h_out)
{
    int warp = (blockIdx.x * blockDim.x + threadIdx.x) >> 5;
    int node = warp;
    int lane = threadIdx.x & 31;
    int hl  = lane & 15;
    int sub = lane >> 4;
    int c = hl * 8;
    unsigned hmask = sub ? 0xffff0000u : 0x0000ffffu;

    __half2 fdh[4], a6[4], a4[4];
    {
        float4 u = *(const float4*)(fd + (size_t)node * HID + c);
        float4 v = *(const float4*)(fd + (size_t)node * HID + c + 4);
        fdh[0] = __floats2half2_rn(u.x, u.y);
        fdh[1] = __floats2half2_rn(u.z, u.w);
        fdh[2] = __floats2half2_rn(v.x, v.y);
        fdh[3] = __floats2half2_rn(v.z, v.w);
        float4 au = *(const float4*)(attn + c);
        float4 av = *(const float4*)(attn + c + 4);
        a6[0] = __floats2half2_rn(0.6f * au.x, 0.6f * au.y);
        a6[1] = __floats2half2_rn(0.6f * au.z, 0.6f * au.w);
        a6[2] = __floats2half2_rn(0.6f * av.x, 0.6f * av.y);
        a6[3] = __floats2half2_rn(0.6f * av.z, 0.6f * av.w);
        a4[0] = __floats2half2_rn(0.4f * au.x, 0.4f * au.y);
        a4[1] = __floats2half2_rn(0.4f * au.z, 0.4f * au.w);
        a4[2] = __floats2half2_rn(0.4f * av.x, 0.4f * av.y);
        a4[3] = __floats2half2_rn(0.4f * av.z, 0.4f * av.w);
    }
    const __half2 hz = __float2half2_rn(0.f);

    int p0 = g_off[node];
    int n  = g_off[node + 1] - p0;

    float ssum = 0.f;
    float acc[8];
#pragma unroll
    for (int j = 0; j < 8; j++) acc[j] = 0.f;

    const char* fsb = (const char*)fsh + c * 2;
    uint4 q0 = make_uint4(0,0,0,0), q1 = q0;
    if (sub     < n) q0 = *(const uint4*)(fsb + g_csrc[p0 + sub]);
    if (sub + 2 < n) q1 = *(const uint4*)(fsb + g_csrc[p0 + sub + 2]);

    for (int i = sub; i < n; i += 2) {
        uint4 q = q0; q0 = q1;
        int inx = i + 4;
        if (inx < n) q1 = *(const uint4*)(fsb + g_csrc[p0 + inx]);

        const __half2* hp = (const __half2*)&q;
        __half2 pdh = hz;
#pragma unroll
        for (int j = 0; j < 4; j++) {
            __half2 x = __hadd2(hp[j], fdh[j]);
            pdh = __hfma2(x, a6[j], pdh);
            pdh = __hfma2(__habs2(x), a4[j], pdh);
        }
        float2 pdf = __half22float2(pdh);
        float pd = pdf.x + pdf.y;
        pd += __shfl_xor_sync(hmask, pd, 1);
        pd += __shfl_xor_sync(hmask, pd, 2);
        float w = __expf(pd);
        ssum += w;
#pragma unroll
        for (int j = 0; j < 4; j++) {
            float2 t2 = __half22float2(hp[j]);
            acc[2 * j]     += w * t2.x;
            acc[2 * j + 1] += w * t2.y;
        }
    }

    ssum += __shfl_xor_sync(0xffffffffu, ssum, 16);
#pragma unroll
    for (int j = 0; j < 8; j++) acc[j] += __shfl_xor_sync(0xffffffffu, acc[j], 16);

    float inv = 1.f / ssum;
    float x[8];
    {
        float4 hu = *(const float4*)(h_in + (size_t)node * HID + c);
        float4 hv = *(const float4*)(h_in + (size_t)node * HID + c + 4);
        x[0] = acc[0] * inv + 2.f * hu.x;
        x[1] = acc[1] * inv + 2.f * hu.y;
        x[2] = acc[2] * inv + 2.f * hu.z;
        x[3] = acc[3] * inv + 2.f * hu.w;
        x[4] = acc[4] * inv + 2.f * hv.x;
        x[5] = acc[5] * inv + 2.f * hv.y;
        x[6] = acc[6] * inv + 2.f * hv.z;
        x[7] = acc[7] * inv + 2.f * hv.w;
    }
    float s1 = 0.f;
#pragma unroll
    for (int j = 0; j < 8; j++) s1 += x[j];
#pragma unroll
    for (int d = 8; d; d >>= 1) s1 += __shfl_xor_sync(0xffffffffu, s1, d);
    float mean = s1 * (1.f / 128.f);
    float dv[8];
    float s2 = 0.f;
#pragma unroll
    for (int j = 0; j < 8; j++) { dv[j] = x[j] - mean; s2 += dv[j] * dv[j]; }
#pragma unroll
    for (int d = 8; d; d >>= 1) s2 += __shfl_xor_sync(0xffffffffu, s2, d);
    float rstd = rsqrtf(s2 * (1.f / 128.f) + 1e-5f);

    float y[8];
    if (sub == 0) {
        float4 gu = *(const float4*)(lng + c);
        float4 gv = *(const float4*)(lng + c + 4);
        float4 bu = *(const float4*)(lnb + c);
        float4 bv = *(const float4*)(lnb + c + 4);
        y[0] = fmaxf(dv[0] * rstd * gu.x + bu.x, 0.f);
        y[1] = fmaxf(dv[1] * rstd * gu.y + bu.y, 0.f);
        y[2] = fmaxf(dv[2] * rstd * gu.z + bu.z, 0.f);
        y[3] = fmaxf(dv[3] * rstd * gu.w + bu.w, 0.f);
        y[4] = fmaxf(dv[4] * rstd * gv.x + bv.x, 0.f);
        y[5] = fmaxf(dv[5] * rstd * gv.y + bv.y, 0.f);
        y[6] = fmaxf(dv[6] * rstd * gv.z + bv.z, 0.f);
        y[7] = fmaxf(dv[7] * rstd * gv.w + bv.w, 0.f);
        *(float4*)(h_out + (size_t)node * HID + c)     = make_float4(y[0], y[1], y[2], y[3]);
        *(float4*)(h_out + (size_t)node * HID + c + 4) = make_float4(y[4], y[5], y[6], y[7]);
    }

    if constexpr (DO_POOL) {
        __shared__ float spool[128];
        for (int i = threadIdx.x; i < 128; i += 256) spool[i] = 0.f;
        __syncthreads();
        if (sub == 0) {
#pragma unroll
            for (int j = 0; j < 8; j++) atomicAdd(&spool[c + j], y[j]);
        }
        __syncthreads();
        if (threadIdx.x < 128) atomicAdd(&G_POOL[threadIdx.x], spool[threadIdx.x]);
    }
}

// ---------------- graph head ----------------
__global__ void head_kernel(
    const float* __restrict__ gf, const float* __restrict__ W_g, const float* __restrict__ b_g,
    const float* __restrict__ W_f1, const float* __restrict__ b_f1,
    const float* __restrict__ W_f2, const float* __restrict__ b_f2,
    float* __restrict__ emb)
{
    __shared__ float comb[256];
    __shared__ float r1[128];
    int t = threadIdx.x;
    float gh = b_g[t];
    for (int k = 0; k < GRAPH_DIM; k++) gh += gf[k] * W_g[k * HID + t];
    comb[128 + t] = gh;
    comb[t] = G_POOL[t] * (1.f / (float)N_NODES);
    __syncthreads();
    float f1 = b_f1[t];
    for (int k = 0; k < 256; k++) f1 += comb[k] * W_f1[k * HID + t];
    r1[t] = fmaxf(f1, 0.f);
    __syncthreads();
    float f2 = b_f2[t];
    for (int k = 0; k < 128; k++) f2 += r1[k] * W_f2[k * HID + t];
    emb[t] = f2;
}

// ---------------- launch ----------------
extern "C" void kernel_launch(void* const* d_in, const int* in_sizes, int n_in,
                              void* d_out, int out_size)
{
    const float* node_feats  = (const float*)d_in[0];
    const float* graph_feats = (const float*)d_in[1];
    const int*   src         = (const int*)d_in[2];
    const int*   dst         = (const int*)d_in[3];
    const float* W_in  = (const float*)d_in[4];
    const float* b_in  = (const float*)d_in[5];
    const float* W_g   = (const float*)d_in[6];
    const float* b_g   = (const float*)d_in[7];
    const float* W_src = (const float*)d_in[8];
    const float* b_src = (const float*)d_in[9];
    const float* W_dst = (const float*)d_in[10];
    const float* b_dst = (const float*)d_in[11];
    const float* attn  = (const float*)d_in[12];
    const float* ln_g  = (const float*)d_in[13];
    const float* ln_b  = (const float*)d_in[14];
    const float* W_f1  = (const float*)d_in[15];
    const float* b_f1  = (const float*)d_in[16];
    const float* W_f2  = (const float*)d_in[17];
    const float* b_f2  = (const float*)d_in[18];

    int E = in_sizes[2];
    if (E > E_MAX) E = E_MAX;

    float *hA, *hB, *fd, *embS;
    __half* fsh;
    uint4 *whs, *whd, *whin;
    int* zeroPtr;
    cudaGetSymbolAddress((void**)&hA,   g_hA);
    cudaGetSymbolAddress((void**)&hB,   g_hB);
    cudaGetSymbolAddress((void**)&fsh,  g_fsh);
    cudaGetSymbolAddress((void**)&fd,   g_fd);
    cudaGetSymbolAddress((void**)&embS, g_emb_scratch);
    cudaGetSymbolAddress((void**)&whs,  g_Whs);
    cudaGetSymbolAddress((void**)&whd,  g_Whd);
    cudaGetSymbolAddress((void**)&whin, g_Whin);
    cudaGetSymbolAddress((void**)&zeroPtr, g_zero);

    float* out = (float*)d_out;
    float* emb_dst;
    float* hfin;
    long long need = (long long)HID + (long long)N_NODES * HID;
    if ((long long)out_size >= need)            { emb_dst = out;  hfin = out + HID; }
    else if (out_size == N_NODES * HID)         { emb_dst = embS; hfin = out; }
    else                                        { emb_dst = out;  hfin = hB; }

    const int smemDual = (64 * 72 + 128 * 72) * 4;   // 55296 B
    const int smem64   = 2 * 128 * (32 + 8) * 4;     // 40960 B (mega gemm_in)

    static cudaStream_t s2 = nullptr;
    static cudaEvent_t evFork = nullptr, evJoin = nullptr;
    static bool init_done = false;
    if (!init_done) {
        cudaFuncSetAttribute(gemm_dual_kernel, cudaFuncAttributeMaxDynamicSharedMemorySize, smemDual);
        cudaFuncSetAttribute(mega_kernel,      cudaFuncAttributeMaxDynamicSharedMemorySize, smem64);
        cudaStreamCreateWithFlags(&s2, cudaStreamNonBlocking);
        cudaEventCreateWithFlags(&evFork, cudaEventDisableTiming);
        cudaEventCreateWithFlags(&evJoin, cudaEventDisableTiming);
        init_done = true;
    }

    // zero deg + pool + done-counter
    cudaMemsetAsync(zeroPtr, 0, (size_t)(N_NODES + HID + 8) * sizeof(int), 0);

    // K1: mega = count (+last-block scan) + weight prep + gemm_in
    int nbCnt = (E + 255) / 256;
    int nbGin = (N_NODES + 127) / 128;
    mega_kernel<<<nbCnt + 208 + nbGin, 256, smem64>>>(
        dst, E, nbCnt, W_in, W_src, W_dst,
        (uint32_t*)whin, (uint32_t*)whs, (uint32_t*)whd,
        node_feats, b_in, hA);

    // Fork: scatter on s2, overlapping layer-0 dual GEMM on main
    cudaEventRecord(evFork, 0);
    cudaStreamWaitEvent(s2, evFork, 0);
    scatter_kernel<<<(E + 255) / 256, 256, 0, s2>>>(src, dst, E);
    cudaEventRecord(evJoin, s2);

    float* hin = hA;
    for (int l = 0; l < 3; l++) {
        dim3 grid((N_NODES + 63) / 64, 2);
        gemm_dual_kernel<<<grid, 256, smemDual>>>(
            hin,
            whs + (size_t)l * (128 * 72 / 4), b_src + (size_t)l * HID, fsh,
            whd + (size_t)l * (128 * 72 / 4), b_dst + (size_t)l * HID, fd);
        if (l == 0) cudaStreamWaitEvent(0, evJoin, 0);   // join scatter before first gat
        float* hout = (l == 2) ? hfin : ((hin == hA) ? hB : hA);
        if (l == 2)
            gat_layer_kernel<true><<<(N_NODES + 7) / 8, 256>>>(
                fsh, fd, hin, attn + (size_t)l * HID,
                ln_g + (size_t)l * HID, ln_b + (size_t)l * HID, hout);
        else
            gat_layer_kernel<false><<<(N_NODES + 7) / 8, 256>>>(
                fsh, fd, hin, attn + (size_t)l * HID,
                ln_g + (size_t)l * HID, ln_b + (size_t)l * HID, hout);
        hin = hout;
    }

    head_kernel<<<1, 128>>>(graph_feats, W_g, b_g, W_f1, b_f1, W_f2, b_f2, emb_dst);
}

// round 13
// speedup vs baseline: 1.0627x; 1.0627x over previous
#include <cuda_runtime.h>
#include <cuda_fp16.h>
#include <math.h>
#include <stdint.h>

#define N_NODES 50000
#define HID 128
#define NODE_DIM 64
#define GRAPH_DIM 32
#define E_MAX 1700000

// ---------------- scratch (static device globals; no allocation) ----------------
__device__ float  g_hA[N_NODES * HID];
__device__ float  g_hB[N_NODES * HID];
__device__ __half g_fsh[N_NODES * HID];
__device__ float  g_fd[N_NODES * HID];
__device__ int    g_off[N_NODES + 1];
__device__ int    g_cur[N_NODES];
__device__ int    g_csrc[E_MAX];          // holds BYTE offsets: src * HID * 2
__device__ float  g_emb_scratch[HID];
// zero-blob: [deg (N)] [pool (HID floats)] [done-counter]
__device__ int    g_zero[N_NODES + HID + 8];
#define G_DEG  (g_zero)
#define G_POOL ((float*)(g_zero + N_NODES))
#define G_CNT  (g_zero + N_NODES + HID)
// prepped fp16 weights, permuted fragment layout. KP2(128)=72 words/row, KP2(64)=40.
__device__ uint4  g_Whs[3][128 * 72 / 4];
__device__ uint4  g_Whd[3][128 * 72 / 4];
__device__ uint4  g_Whin[128 * 40 / 4];

// ---------------- fp16 tensor-core GEMM core (m16n8k16, fp32 accum) ----------------
__device__ __forceinline__ void mma_f16(float* c, const uint32_t* a, const uint32_t* b) {
    asm volatile(
        "mma.sync.aligned.m16n8k16.row.col.f32.f16.f16.f32 "
        "{%0,%1,%2,%3}, {%4,%5,%6,%7}, {%8,%9}, {%0,%1,%2,%3};"
        : "+f"(c[0]), "+f"(c[1]), "+f"(c[2]), "+f"(c[3])
        : "r"(a[0]), "r"(a[1]), "r"(a[2]), "r"(a[3]), "r"(b[0]), "r"(b[1]));
}

// A tile loader: fp32 [TR x K] gmem -> permuted fp16 smem (KP2 = K/2+8 words/row)
template <int K, int TR>
__device__ __forceinline__ void load_a_tile(const float* __restrict__ A, uint32_t* sA, int row0) {
    constexpr int KP2 = K / 2 + 8;
    const int o0tab[4] = {0, 4, 1, 5};
    const int o1tab[4] = {2, 6, 3, 7};
    int tid = threadIdx.x;
    for (int i = tid; i < TR * (K / 4); i += 256) {
        int r = i / (K / 4);
        int q = i % (K / 4);
        int row = row0 + r;
        float4 v = make_float4(0.f, 0.f, 0.f, 0.f);
        if (row < N_NODES) v = *(const float4*)(A + (size_t)row * K + q * 4);
        int base = r * KP2 + (q >> 2) * 8;
        __half2 h01 = __floats2half2_rn(v.x, v.y);
        __half2 h23 = __floats2half2_rn(v.z, v.w);
        sA[base + o0tab[q & 3]] = *(uint32_t*)&h01;
        sA[base + o1tab[q & 3]] = *(uint32_t*)&h23;
    }
}

// mainloop + epilogue over a TR x 128 tile. Ch != nullptr -> fp16 output, else fp32 to Cf.
template <int K, int TR>
__device__ __forceinline__ void gemm_core(const uint32_t* sA, const uint32_t* sB, int row0,
                                          const float* __restrict__ bias,
                                          float* __restrict__ Cf, __half* __restrict__ Ch) {
    constexpr int KP2 = K / 2 + 8;
    constexpr int RPM = TR / 4;     // rows per mwarp
    constexpr int NT  = TR / 64;    // 16-row pair groups per mwarp
    int tid = threadIdx.x;
    int warp = tid >> 5;
    int lane = tid & 31;
    int mwarp = warp >> 1;
    int nwarp = warp & 1;
    int g = lane >> 2;
    int tg = lane & 3;

    float acc[NT][8][4];
#pragma unroll
    for (int t = 0; t < NT; t++)
#pragma unroll
        for (int j = 0; j < 8; j++) { acc[t][j][0] = acc[t][j][1] = acc[t][j][2] = acc[t][j][3] = 0.f; }

    int rb = mwarp * RPM + g;
#pragma unroll
    for (int ks = 0; ks < K / 16; ks++) {
        int kk = ks * 8 + tg * 2;
        uint32_t afr[NT][4];
#pragma unroll
        for (int t = 0; t < NT; t++) {
            uint2 a0 = *(const uint2*)(sA + (rb + t * 16)     * KP2 + kk);
            uint2 a1 = *(const uint2*)(sA + (rb + t * 16 + 8) * KP2 + kk);
            afr[t][0] = a0.x; afr[t][1] = a1.x; afr[t][2] = a0.y; afr[t][3] = a1.y;
        }
        uint32_t bfr[8][2];
#pragma unroll
        for (int j = 0; j < 8; j++) {
            int n0 = nwarp * 64 + j * 8 + g;
            uint2 b = *(const uint2*)(sB + n0 * KP2 + kk);
            bfr[j][0] = b.x; bfr[j][1] = b.y;
        }
#pragma unroll
        for (int t = 0; t < NT; t++)
#pragma unroll
            for (int j = 0; j < 8; j++) mma_f16(acc[t][j], afr[t], bfr[j]);
    }

#pragma unroll
    for (int t = 0; t < NT; t++) {
        int rbase = row0 + mwarp * RPM + t * 16 + g;
#pragma unroll
        for (int j = 0; j < 8; j++) {
            int col = nwarp * 64 + j * 8 + tg * 2;
            float bx = __ldg(bias + col);
            float by = __ldg(bias + col + 1);
            float v0x = acc[t][j][0] + bx, v0y = acc[t][j][1] + by;
            float v1x = acc[t][j][2] + bx, v1y = acc[t][j][3] + by;
            if (Ch) {
                if (rbase < N_NODES)
                    *(__half2*)(Ch + (size_t)rbase * HID + col) = __floats2half2_rn(v0x, v0y);
                if (rbase + 8 < N_NODES)
                    *(__half2*)(Ch + (size_t)(rbase + 8) * HID + col) = __floats2half2_rn(v1x, v1y);
            } else {
                if (rbase < N_NODES)
                    *(float2*)(Cf + (size_t)rbase * HID + col) = make_float2(v0x, v0y);
                if (rbase + 8 < N_NODES)
                    *(float2*)(Cf + (size_t)(rbase + 8) * HID + col) = make_float2(v1x, v1y);
            }
        }
    }
}

// ---------------- MEGA kernel: count + (last block) scan + weight prep + gemm_in ----------
__global__ void __launch_bounds__(256) mega_kernel(
    const int* __restrict__ dst, int E, int nbCnt,
    const float* __restrict__ W_in, const float* __restrict__ W_src, const float* __restrict__ W_dst,
    uint32_t* __restrict__ o_in, uint32_t* __restrict__ o_src, uint32_t* __restrict__ o_dst,
    const float* __restrict__ node_feats, const float* __restrict__ b_in, float* __restrict__ hA)
{
    int bx = blockIdx.x;
    int tid = threadIdx.x;

    if (bx < nbCnt) {
        int e = bx * 256 + tid;
        if (e < E) atomicAdd(&G_DEG[dst[e]], 1);
        __syncthreads();
        __threadfence();
        __shared__ int is_last;
        if (tid == 0) {
            int d = atomicAdd(G_CNT, 1);
            is_last = (d == nbCnt - 1);
        }
        __syncthreads();
        if (is_last) {
            __threadfence();
            __shared__ int sums[256];
            const int CH = (N_NODES + 255) / 256;
            int st = tid * CH;
            int en = st + CH; if (en > N_NODES) en = N_NODES;
            if (st > N_NODES) st = N_NODES;
            int s = 0;
            for (int i = st; i < en; i++) s += G_DEG[i];
            sums[tid] = s;
            __syncthreads();
            for (int d = 1; d < 256; d <<= 1) {
                int v = (tid >= d) ? sums[tid - d] : 0;
                __syncthreads();
                sums[tid] += v;
                __syncthreads();
            }
            int run = (tid == 0) ? 0 : sums[tid - 1];
            for (int i = st; i < en; i++) {
                g_off[i] = run;
                g_cur[i] = run;
                run += G_DEG[i];
            }
            if (tid == 255) g_off[N_NODES] = sums[255];
        }
        return;
    }
    bx -= nbCnt;

    if (bx < 208) {
        const float* W; uint32_t* out; int K; int inner;
        if (bx < 16) { W = W_in; out = o_in; K = 64; inner = bx; }
        else {
            int b2 = bx - 16;
            int which = b2 >> 5;
            inner = b2 & 31;
            int l = which % 3;
            if (which < 3) { W = W_src + (size_t)l * HID * HID; out = o_src + (size_t)l * (128 * 72); }
            else           { W = W_dst + (size_t)l * HID * HID; out = o_dst + (size_t)l * (128 * 72); }
            K = 128;
        }
        int half_k = K >> 1;
        int idx = inner * 256 + tid;
        if (idx >= 128 * half_k) return;
        int n = idx / half_k;
        int k = (idx % half_k) * 2;
        float x = W[(size_t)k * HID + n];
        float y = W[(size_t)(k + 1) * HID + n];
        int KP2 = half_k + 8;
        int uu = (k & 15) >> 1;
        int o = (uu & 3) * 2 + (uu >> 2);
        __half2 h = __floats2half2_rn(x, y);
        out[n * KP2 + (k >> 4) * 8 + o] = *(uint32_t*)&h;
        return;
    }
    bx -= 208;

    {
        constexpr int KP2 = 64 / 2 + 8;
        extern __shared__ uint32_t smem_u[];
        uint32_t* sA = smem_u;
        uint32_t* sB = smem_u + 128 * KP2;
        int row0 = bx * 128;
        load_a_tile<64, 128>(node_feats, sA, row0);
        for (int i = tid; i < 128 * 32; i += 256) {
            int n = i >> 5;
            int k = (i & 31) * 2;
            float x = W_in[(size_t)k * HID + n];
            float y = W_in[(size_t)(k + 1) * HID + n];
            int uu = (k & 15) >> 1;
            int o = (uu & 3) * 2 + (uu >> 2);
            __half2 h = __floats2half2_rn(x, y);
            sB[n * KP2 + (k >> 4) * 8 + o] = *(uint32_t*)&h;
        }
        __syncthreads();
        gemm_core<64, 128>(sA, sB, row0, b_in, hA, nullptr);
    }
}

// ---------------- scatter (stores BYTE offsets src*256) ----------------
__global__ void scatter_kernel(const int* __restrict__ src, const int* __restrict__ dst, int E) {
    int e = blockIdx.x * blockDim.x + threadIdx.x;
    if (e < E) {
        int d = dst[e];
        int pos = atomicAdd(&g_cur[d], 1);
        g_csrc[pos] = src[e] << 8;          // HID * sizeof(half) = 256
    }
}

// ---------------- dual GEMM: 64-row tiles for 3 CTAs/SM ----------------
__global__ void __launch_bounds__(256, 3) gemm_dual_kernel(
    const float* __restrict__ A,
    const uint4* __restrict__ Wh1, const float* __restrict__ b1, __half* __restrict__ C1h,
    const uint4* __restrict__ Wh2, const float* __restrict__ b2, float* __restrict__ C2)
{
    constexpr int KP2 = 128 / 2 + 8;      // 72
    extern __shared__ uint32_t smem_u[];
    uint32_t* sA = smem_u;                // [64][72]
    uint32_t* sB = smem_u + 64 * KP2;     // [128][72]

    const uint4* Wh; const float* bias;
    if (blockIdx.y == 0) { Wh = Wh1; bias = b1; }
    else                 { Wh = Wh2; bias = b2; }

    int row0 = blockIdx.x * 64;
    load_a_tile<128, 64>(A, sA, row0);
    {
        uint4* dstp = (uint4*)sB;
        for (int i = threadIdx.x; i < 128 * KP2 / 4; i += 256) dstp[i] = Wh[i];
    }
    __syncthreads();
    if (blockIdx.y == 0) gemm_core<128, 64>(sA, sB, row0, bias, nullptr, C1h);
    else                 gemm_core<128, 64>(sA, sB, row0, bias, C2, nullptr);
}

// ---------------- GATv2 layer: warp/node, half-warp/edge, half2 min/max logits (R11 best) --
template <bool DO_POOL>
__global__ void __launch_bounds__(256) gat_layer_kernel(
    const __half* __restrict__ fsh, const float* __restrict__ fd,
    const float* __restrict__ h_in, const float* __restrict__ attn,
    const float* __restrict__ lng, const float* __restrict__ lnb,
    float* __restrict__ h_out)
{
    int warp = (blockIdx.x * blockDim.x + threadIdx.x) >> 5;
    int node = warp;
    int lane = threadIdx.x & 31;
    int hl  = lane & 15;
    int sub = lane >> 4;
    int c = hl * 8;
    unsigned hmask = sub ? 0xffff0000u : 0x0000ffffu;

    // fd, attn as half2 (logit path); conversions once per node
    __half2 fdh[4], ah[4];
    {
        float4 u = *(const float4*)(fd + (size_t)node * HID + c);
        float4 v = *(const float4*)(fd + (size_t)node * HID + c + 4);
        fdh[0] = __floats2half2_rn(u.x, u.y);
        fdh[1] = __floats2half2_rn(u.z, u.w);
        fdh[2] = __floats2half2_rn(v.x, v.y);
        fdh[3] = __floats2half2_rn(v.z, v.w);
        float4 au = *(const float4*)(attn + c);
        float4 av = *(const float4*)(attn + c + 4);
        ah[0] = __floats2half2_rn(au.x, au.y);
        ah[1] = __floats2half2_rn(au.z, au.w);
        ah[2] = __floats2half2_rn(av.x, av.y);
        ah[3] = __floats2half2_rn(av.z, av.w);
    }
    const __half2 hz  = __float2half2_rn(0.f);
    const __half2 h02 = __float2half2_rn(0.2f);

    int p0 = g_off[node];
    int n  = g_off[node + 1] - p0;

    float ssum = 0.f;
    float acc[8];
#pragma unroll
    for (int j = 0; j < 8; j++) acc[j] = 0.f;

    const char* fsb = (const char*)fsh + c * 2;   // lane byte base
    uint4 q0 = make_uint4(0,0,0,0), q1 = q0;
    if (sub     < n) q0 = *(const uint4*)(fsb + g_csrc[p0 + sub]);
    if (sub + 2 < n) q1 = *(const uint4*)(fsb + g_csrc[p0 + sub + 2]);

    for (int i = sub; i < n; i += 2) {
        uint4 q = q0; q0 = q1;
        int inx = i + 4;
        if (inx < n) q1 = *(const uint4*)(fsb + g_csrc[p0 + inx]);

        const __half2* hp = (const __half2*)&q;
        // logits fully in half2: x = f+fd; leaky = max(x,0) + 0.2*min(x,0); dot with a
        __half2 pdh = hz;
#pragma unroll
        for (int j = 0; j < 4; j++) {
            __half2 x = __hadd2(hp[j], fdh[j]);
            __half2 t = __hfma2(__hmin2(x, hz), h02, __hmax2(x, hz));
            pdh = __hfma2(t, ah[j], pdh);
        }
        float2 pdf = __half22float2(pdh);
        float pd = pdf.x + pdf.y;
        pd += __shfl_xor_sync(hmask, pd, 1);
        pd += __shfl_xor_sync(hmask, pd, 2);
        float w = __expf(pd);
        ssum += w;
#pragma unroll
        for (int j = 0; j < 4; j++) {
            float2 t2 = __half22float2(hp[j]);
            acc[2 * j]     += w * t2.x;
            acc[2 * j + 1] += w * t2.y;
        }
    }

    ssum += __shfl_xor_sync(0xffffffffu, ssum, 16);
#pragma unroll
    for (int j = 0; j < 8; j++) acc[j] += __shfl_xor_sync(0xffffffffu, acc[j], 16);

    float inv = 1.f / ssum;
    float x[8];
    {
        float4 hu = *(const float4*)(h_in + (size_t)node * HID + c);
        float4 hv = *(const float4*)(h_in + (size_t)node * HID + c + 4);
        x[0] = acc[0] * inv + 2.f * hu.x;
        x[1] = acc[1] * inv + 2.f * hu.y;
        x[2] = acc[2] * inv + 2.f * hu.z;
        x[3] = acc[3] * inv + 2.f * hu.w;
        x[4] = acc[4] * inv + 2.f * hv.x;
        x[5] = acc[5] * inv + 2.f * hv.y;
        x[6] = acc[6] * inv + 2.f * hv.z;
        x[7] = acc[7] * inv + 2.f * hv.w;
    }
    float s1 = 0.f;
#pragma unroll
    for (int j = 0; j < 8; j++) s1 += x[j];
#pragma unroll
    for (int d = 8; d; d >>= 1) s1 += __shfl_xor_sync(0xffffffffu, s1, d);
    float mean = s1 * (1.f / 128.f);
    float dv[8];
    float s2 = 0.f;
#pragma unroll
    for (int j = 0; j < 8; j++) { dv[j] = x[j] - mean; s2 += dv[j] * dv[j]; }
#pragma unroll
    for (int d = 8; d; d >>= 1) s2 += __shfl_xor_sync(0xffffffffu, s2, d);
    float rstd = rsqrtf(s2 * (1.f / 128.f) + 1e-5f);

    float y[8];
    if (sub == 0) {
        float4 gu = *(const float4*)(lng + c);
        float4 gv = *(const float4*)(lng + c + 4);
        float4 bu = *(const float4*)(lnb + c);
        float4 bv = *(const float4*)(lnb + c + 4);
        y[0] = fmaxf(dv[0] * rstd * gu.x + bu.x, 0.f);
        y[1] = fmaxf(dv[1] * rstd * gu.y + bu.y, 0.f);
        y[2] = fmaxf(dv[2] * rstd * gu.z + bu.z, 0.f);
        y[3] = fmaxf(dv[3] * rstd * gu.w + bu.w, 0.f);
        y[4] = fmaxf(dv[4] * rstd * gv.x + bv.x, 0.f);
        y[5] = fmaxf(dv[5] * rstd * gv.y + bv.y, 0.f);
        y[6] = fmaxf(dv[6] * rstd * gv.z + bv.z, 0.f);
        y[7] = fmaxf(dv[7] * rstd * gv.w + bv.w, 0.f);
        *(float4*)(h_out + (size_t)node * HID + c)     = make_float4(y[0], y[1], y[2], y[3]);
        *(float4*)(h_out + (size_t)node * HID + c + 4) = make_float4(y[4], y[5], y[6], y[7]);
    }

    if constexpr (DO_POOL) {
        __shared__ float spool[128];
        for (int i = threadIdx.x; i < 128; i += 256) spool[i] = 0.f;
        __syncthreads();
        if (sub == 0) {
#pragma unroll
            for (int j = 0; j < 8; j++) atomicAdd(&spool[c + j], y[j]);
        }
        __syncthreads();
        if (threadIdx.x < 128) atomicAdd(&G_POOL[threadIdx.x], spool[threadIdx.x]);
    }
}

// ---------------- graph head ----------------
__global__ void head_kernel(
    const float* __restrict__ gf, const float* __restrict__ W_g, const float* __restrict__ b_g,
    const float* __restrict__ W_f1, const float* __restrict__ b_f1,
    const float* __restrict__ W_f2, const float* __restrict__ b_f2,
    float* __restrict__ emb)
{
    __shared__ float comb[256];
    __shared__ float r1[128];
    int t = threadIdx.x;
    float gh = b_g[t];
    for (int k = 0; k < GRAPH_DIM; k++) gh += gf[k] * W_g[k * HID + t];
    comb[128 + t] = gh;
    comb[t] = G_POOL[t] * (1.f / (float)N_NODES);
    __syncthreads();
    float f1 = b_f1[t];
    for (int k = 0; k < 256; k++) f1 += comb[k] * W_f1[k * HID + t];
    r1[t] = fmaxf(f1, 0.f);
    __syncthreads();
    float f2 = b_f2[t];
    for (int k = 0; k < 128; k++) f2 += r1[k] * W_f2[k * HID + t];
    emb[t] = f2;
}

// ---------------- launch ----------------
extern "C" void kernel_launch(void* const* d_in, const int* in_sizes, int n_in,
                              void* d_out, int out_size)
{
    const float* node_feats  = (const float*)d_in[0];
    const float* graph_feats = (const float*)d_in[1];
    const int*   src         = (const int*)d_in[2];
    const int*   dst         = (const int*)d_in[3];
    const float* W_in  = (const float*)d_in[4];
    const float* b_in  = (const float*)d_in[5];
    const float* W_g   = (const float*)d_in[6];
    const float* b_g   = (const float*)d_in[7];
    const float* W_src = (const float*)d_in[8];
    const float* b_src = (const float*)d_in[9];
    const float* W_dst = (const float*)d_in[10];
    const float* b_dst = (const float*)d_in[11];
    const float* attn  = (const float*)d_in[12];
    const float* ln_g  = (const float*)d_in[13];
    const float* ln_b  = (const float*)d_in[14];
    const float* W_f1  = (const float*)d_in[15];
    const float* b_f1  = (const float*)d_in[16];
    const float* W_f2  = (const float*)d_in[17];
    const float* b_f2  = (const float*)d_in[18];

    int E = in_sizes[2];
    if (E > E_MAX) E = E_MAX;

    float *hA, *hB, *fd, *embS;
    __half* fsh;
    uint4 *whs, *whd, *whin;
    int* zeroPtr;
    cudaGetSymbolAddress((void**)&hA,   g_hA);
    cudaGetSymbolAddress((void**)&hB,   g_hB);
    cudaGetSymbolAddress((void**)&fsh,  g_fsh);
    cudaGetSymbolAddress((void**)&fd,   g_fd);
    cudaGetSymbolAddress((void**)&embS, g_emb_scratch);
    cudaGetSymbolAddress((void**)&whs,  g_Whs);
    cudaGetSymbolAddress((void**)&whd,  g_Whd);
    cudaGetSymbolAddress((void**)&whin, g_Whin);
    cudaGetSymbolAddress((void**)&zeroPtr, g_zero);

    float* out = (float*)d_out;
    float* emb_dst;
    float* hfin;
    long long need = (long long)HID + (long long)N_NODES * HID;
    if ((long long)out_size >= need)            { emb_dst = out;  hfin = out + HID; }
    else if (out_size == N_NODES * HID)         { emb_dst = embS; hfin = out; }
    else                                        { emb_dst = out;  hfin = hB; }

    const int smemDual = (64 * 72 + 128 * 72) * 4;   // 55296 B
    const int smem64   = 2 * 128 * (32 + 8) * 4;     // 40960 B (mega gemm_in)

    static cudaStream_t s2 = nullptr;
    static cudaEvent_t evFork = nullptr, evJoin = nullptr;
    static bool init_done = false;
    if (!init_done) {
        cudaFuncSetAttribute(gemm_dual_kernel, cudaFuncAttributeMaxDynamicSharedMemorySize, smemDual);
        cudaFuncSetAttribute(mega_kernel,      cudaFuncAttributeMaxDynamicSharedMemorySize, smem64);
        cudaStreamCreateWithFlags(&s2, cudaStreamNonBlocking);
        cudaEventCreateWithFlags(&evFork, cudaEventDisableTiming);
        cudaEventCreateWithFlags(&evJoin, cudaEventDisableTiming);
        init_done = true;
    }

    // zero deg + pool + done-counter
    cudaMemsetAsync(zeroPtr, 0, (size_t)(N_NODES + HID + 8) * sizeof(int), 0);

    // K1: mega = count (+last-block scan) + weight prep + gemm_in
    int nbCnt = (E + 255) / 256;
    int nbGin = (N_NODES + 127) / 128;
    mega_kernel<<<nbCnt + 208 + nbGin, 256, smem64>>>(
        dst, E, nbCnt, W_in, W_src, W_dst,
        (uint32_t*)whin, (uint32_t*)whs, (uint32_t*)whd,
        node_feats, b_in, hA);

    // Fork: scatter on s2, overlapping layer-0 dual GEMM on main
    cudaEventRecord(evFork, 0);
    cudaStreamWaitEvent(s2, evFork, 0);
    scatter_kernel<<<(E + 255) / 256, 256, 0, s2>>>(src, dst, E);
    cudaEventRecord(evJoin, s2);

    float* hin = hA;
    for (int l = 0; l < 3; l++) {
        dim3 grid((N_NODES + 63) / 64, 2);
        gemm_dual_kernel<<<grid, 256, smemDual>>>(
            hin,
            whs + (size_t)l * (128 * 72 / 4), b_src + (size_t)l * HID, fsh,
            whd + (size_t)l * (128 * 72 / 4), b_dst + (size_t)l * HID, fd);
        if (l == 0) cudaStreamWaitEvent(0, evJoin, 0);   // join scatter before first gat
        float* hout = (l == 2) ? hfin : ((hin == hA) ? hB : hA);
        if (l == 2)
            gat_layer_kernel<true><<<(N_NODES + 7) / 8, 256>>>(
                fsh, fd, hin, attn + (size_t)l * HID,
                ln_g + (size_t)l * HID, ln_b + (size_t)l * HID, hout);
        else
            gat_layer_kernel<false><<<(N_NODES + 7) / 8, 256>>>(
                fsh, fd, hin, attn + (size_t)l * HID,
                ln_g + (size_t)l * HID, ln_b + (size_t)l * HID, hout);
        hin = hout;
    }

    head_kernel<<<1, 128>>>(graph_feats, W_g, b_g, W_f1, b_f1, W_f2, b_f2, emb_dst);
}